// round 9
// baseline (speedup 1.0000x reference)
#include <cuda_runtime.h>
#include <cuda_fp16.h>

#define N_NODES 100000
#define N_EDGES 1600000
#define NUM_GRAPHS 4096
#define HID 128
#define F_IN 11
#define F_PAD 12
#define F_OUT 19
#define Z_PAD 24                 // halves per z row (48B, 16B-aligned)

#define SCAN_CHUNK 2048
#define SCAN_NBLK ((N_NODES + SCAN_CHUNK - 1) / SCAN_CHUNK)   // 49

// ---------------- scratch (static device globals; no allocation) ----------------
__device__ int    g_cnt[N_NODES];
__device__ int    g_fill[N_NODES];
__device__ float  g_dinv[N_NODES];
__device__ int    g_rowptr[N_NODES + 1];
__device__ int    g_csr[N_EDGES];                  // src only
__device__ float  g_x12[N_NODES * F_PAD];          // x * dinv, padded to 12
__device__ __half g_z[N_NODES * Z_PAD];            // z = (relu(h1)*dinv) @ Wc, fp16
__device__ float  g_q[NUM_GRAPHS * 20];            // pooled z (20 = F_OUT padded)
__device__ float  g_gcnt[NUM_GRAPHS];
__device__ float  g_Wc[HID * F_OUT];
__device__ float  g_bc[F_OUT];
__device__ int    g_bsum[64];

typedef unsigned long long ull;
__device__ __forceinline__ ull fma2(ull a, ull b, ull c) {
    ull d;
    asm("fma.rn.f32x2 %0, %1, %2, %3;" : "=l"(d) : "l"(a), "l"(b), "l"(c));
    return d;
}
__device__ __forceinline__ ull pack2(float lo, float hi) {
    ull d;
    asm("mov.b64 %0, {%1, %2};" : "=l"(d) : "f"(lo), "f"(hi));
    return d;
}
__device__ __forceinline__ void unpack2(ull v, float& lo, float& hi) {
    asm("mov.b64 {%0, %1}, %2;" : "=f"(lo), "=f"(hi) : "l"(v));
}

// ---------------- kernels ----------------

// init: zero counters/accumulators, precompute Wc/bc
__global__ void k_init(const float* __restrict__ W2, const float* __restrict__ b2,
                       const float* __restrict__ Wlin, const float* __restrict__ blin) {
    int i = blockIdx.x * blockDim.x + threadIdx.x;
    int stride = gridDim.x * blockDim.x;
    for (int j = i; j < N_NODES; j += stride) { g_cnt[j] = 0; g_fill[j] = 0; }
    for (int j = i; j < NUM_GRAPHS * 20; j += stride) g_q[j] = 0.f;
    for (int j = i; j < NUM_GRAPHS; j += stride) g_gcnt[j] = 0.f;
    for (int j = i; j < HID * F_OUT + F_OUT; j += stride) {
        if (j < HID * F_OUT) {
            int k = j / F_OUT, o = j - k * F_OUT;
            float s = 0.f;
#pragma unroll 8
            for (int m = 0; m < HID; m++) s = fmaf(W2[k * HID + m], Wlin[m * F_OUT + o], s);
            g_Wc[j] = s;
        } else {
            int o = j - HID * F_OUT;
            float s = blin[o];
#pragma unroll 8
            for (int m = 0; m < HID; m++) s = fmaf(b2[m], Wlin[m * F_OUT + o], s);
            g_bc[o] = s;
        }
    }
}

// edge in-degree count + per-graph node count (int4 vectorized)
__global__ void k_count(const int* __restrict__ dst, const int* __restrict__ batch) {
    int i = blockIdx.x * blockDim.x + threadIdx.x;
    int stride = gridDim.x * blockDim.x;
    const int4* dst4 = (const int4*)dst;
    for (int e = i; e < N_EDGES / 4; e += stride) {
        int4 d = dst4[e];
        atomicAdd(&g_cnt[d.x], 1);
        atomicAdd(&g_cnt[d.y], 1);
        atomicAdd(&g_cnt[d.z], 1);
        atomicAdd(&g_cnt[d.w], 1);
    }
    const int4* b4 = (const int4*)batch;
    for (int n = i; n < N_NODES / 4; n += stride) {
        int4 b = b4[n];
        if (b.x == b.w) {
            atomicAdd(&g_gcnt[b.x], 4.f);
        } else {
            atomicAdd(&g_gcnt[b.x], 1.f);
            atomicAdd(&g_gcnt[b.y], 1.f);
            atomicAdd(&g_gcnt[b.z], 1.f);
            atomicAdd(&g_gcnt[b.w], 1.f);
        }
    }
}

// ---- scan phase 1 (+ dinv fused) ----
__global__ void k_scan1() {
    __shared__ int sm[1024];
    int t = threadIdx.x;
    int base = blockIdx.x * SCAN_CHUNK;
    int i0 = base + 2 * t, i1 = i0 + 1;
    int v0 = (i0 < N_NODES) ? g_cnt[i0] : 0;
    int v1 = (i1 < N_NODES) ? g_cnt[i1] : 0;
    if (i0 < N_NODES) g_dinv[i0] = rsqrtf((float)(v0 + 1));
    if (i1 < N_NODES) g_dinv[i1] = rsqrtf((float)(v1 + 1));
    int s = v0 + v1;
    sm[t] = s;
    __syncthreads();
    for (int off = 1; off < 1024; off <<= 1) {
        int add = (t >= off) ? sm[t - off] : 0;
        __syncthreads();
        sm[t] += add;
        __syncthreads();
    }
    int excl = sm[t] - s;
    if (i0 < N_NODES) g_rowptr[i0] = excl;
    if (i1 < N_NODES) g_rowptr[i1] = excl + v0;
    if (t == 1023) g_bsum[blockIdx.x] = sm[t];
}

// ---- scan phases 2+3 merged ----
__global__ void k_scan23() {
    __shared__ int sm[64];
    int t = threadIdx.x;
    if (t < 64) sm[t] = (t < SCAN_NBLK) ? g_bsum[t] : 0;
    __syncthreads();
    if (t == 0) {
        int run = 0;
#pragma unroll
        for (int j = 0; j < SCAN_NBLK; j++) { int v = sm[j]; sm[j] = run; run += v; }
    }
    __syncthreads();
    int i = blockIdx.x * blockDim.x + t;
    if (i < N_NODES) g_rowptr[i] += sm[i >> 11];
    if (i == 0) g_rowptr[N_NODES] = N_EDGES;
}

// CSR fill (src only, int4 reads) + build x12 = x * dinv (padded)
__global__ void k_fill(const int* __restrict__ src, const int* __restrict__ dst,
                       const float* __restrict__ x) {
    int i = blockIdx.x * blockDim.x + threadIdx.x;
    int stride = gridDim.x * blockDim.x;
    const int4* src4 = (const int4*)src;
    const int4* dst4 = (const int4*)dst;
    for (int e = i; e < N_EDGES / 4; e += stride) {
        int4 s = src4[e];
        int4 d = dst4[e];
        g_csr[g_rowptr[d.x] + atomicAdd(&g_fill[d.x], 1)] = s.x;
        g_csr[g_rowptr[d.y] + atomicAdd(&g_fill[d.y], 1)] = s.y;
        g_csr[g_rowptr[d.z] + atomicAdd(&g_fill[d.z], 1)] = s.z;
        g_csr[g_rowptr[d.w] + atomicAdd(&g_fill[d.w], 1)] = s.w;
    }
    for (int n = i; n < N_NODES; n += stride) {
        float di = g_dinv[n];
        float r[F_PAD];
#pragma unroll
        for (int f = 0; f < F_IN; f++) r[f] = x[n * F_IN + f] * di;
        r[11] = 0.f;
        *(float4*)&g_x12[n * F_PAD]     = make_float4(r[0], r[1], r[2],  r[3]);
        *(float4*)&g_x12[n * F_PAD + 4] = make_float4(r[4], r[5], r[6],  r[7]);
        *(float4*)&g_x12[n * F_PAD + 8] = make_float4(r[8], r[9], r[10], r[11]);
    }
}

// ---- fused layer 1: aggregate -> GEMM1 -> relu*dinv (smem fp16) -> z = h1' @ Wc -> g_z ----
__global__ void __launch_bounds__(128) k_layer1(const float* __restrict__ W1,
                                                const float* __restrict__ b1) {
    __shared__ float  sw[F_IN][HID];
    __shared__ float  sb[HID];
    __shared__ float  sa[128][13];
    __shared__ float  sdi[128];
    __shared__ __half sh1[128][130];   // 260B row stride -> conflict-free column access
    __shared__ ull    swc[64][F_OUT];  // (Wc[2k][o], Wc[2k+1][o]) f32 pairs
    int tid = threadIdx.x;
    for (int j = tid; j < F_IN * HID; j += 128) sw[j / HID][j % HID] = W1[j];
    for (int j = tid; j < HID; j += 128) sb[j] = b1[j];
    for (int j = tid; j < 64 * F_OUT; j += 128) {
        int k2 = j / F_OUT, o = j - k2 * F_OUT;
        swc[k2][o] = pack2(g_Wc[(2 * k2) * F_OUT + o], g_Wc[(2 * k2 + 1) * F_OUT + o]);
    }

    // phase 1: per-thread aggregation of pre-scaled x
    int node = blockIdx.x * 128 + tid;
    if (node < N_NODES) {
        float di = g_dinv[node];
        sdi[tid] = di;
        float4 a0 = *(const float4*)&g_x12[node * F_PAD];
        float4 a1 = *(const float4*)&g_x12[node * F_PAD + 4];
        float4 a2 = *(const float4*)&g_x12[node * F_PAD + 8];
        int rs = g_rowptr[node], re = g_rowptr[node + 1];
#pragma unroll 2
        for (int e = rs; e < re; e++) {
            int s = g_csr[e];
            float4 x0 = *(const float4*)&g_x12[s * F_PAD];
            float4 x1 = *(const float4*)&g_x12[s * F_PAD + 4];
            float4 x2 = *(const float4*)&g_x12[s * F_PAD + 8];
            a0.x += x0.x; a0.y += x0.y; a0.z += x0.z; a0.w += x0.w;
            a1.x += x1.x; a1.y += x1.y; a1.z += x1.z; a1.w += x1.w;
            a2.x += x2.x; a2.y += x2.y; a2.z += x2.z;
        }
        sa[tid][0] = a0.x * di; sa[tid][1] = a0.y * di; sa[tid][2]  = a0.z * di; sa[tid][3] = a0.w * di;
        sa[tid][4] = a1.x * di; sa[tid][5] = a1.y * di; sa[tid][6]  = a1.z * di; sa[tid][7] = a1.w * di;
        sa[tid][8] = a2.x * di; sa[tid][9] = a2.y * di; sa[tid][10] = a2.z * di;
    }
    __syncthreads();

    // GEMM1: warp wi computes nodes wi*32..+31; lane l -> features 4l..4l+3; h1' -> sh1 fp16
    {
        int wi = tid >> 5, l = tid & 31;
        int f = l * 4;
        float4 bias = *(const float4*)&sb[f];
#pragma unroll 4
        for (int i = 0; i < 32; i++) {
            int nn = wi * 32 + i;
            int nd = blockIdx.x * 128 + nn;
            if (nd >= N_NODES) break;
            float4 acc = bias;
#pragma unroll
            for (int k = 0; k < F_IN; k++) {
                float a = sa[nn][k];
                float4 w = *(const float4*)&sw[k][f];
                acc.x = fmaf(a, w.x, acc.x);
                acc.y = fmaf(a, w.y, acc.y);
                acc.z = fmaf(a, w.z, acc.z);
                acc.w = fmaf(a, w.w, acc.w);
            }
            float di = sdi[nn];
            sh1[nn][f]     = __float2half_rn(fmaxf(acc.x, 0.f) * di);
            sh1[nn][f + 1] = __float2half_rn(fmaxf(acc.y, 0.f) * di);
            sh1[nn][f + 2] = __float2half_rn(fmaxf(acc.z, 0.f) * di);
            sh1[nn][f + 3] = __float2half_rn(fmaxf(acc.w, 0.f) * di);
        }
    }
    __syncthreads();

    // phase 2: z[node] = sh1[node] @ Wc  (f32x2, Wc broadcast from smem)
    if (node < N_NODES) {
        ull acc[F_OUT];
#pragma unroll
        for (int o = 0; o < F_OUT; o++) acc[o] = 0ull;
        for (int k2 = 0; k2 < 64; k2++) {
            float2 af = __half22float2(*(__half2*)&sh1[tid][2 * k2]);
            ull aa = pack2(af.x, af.y);
#pragma unroll
            for (int o = 0; o < F_OUT; o++) acc[o] = fma2(aa, swc[k2][o], acc[o]);
        }
        __half zh[Z_PAD];
#pragma unroll
        for (int o = 0; o < F_OUT; o++) {
            float lo, hi;
            unpack2(acc[o], lo, hi);
            zh[o] = __float2half_rn(lo + hi);
        }
#pragma unroll
        for (int o = F_OUT; o < Z_PAD; o++) zh[o] = __float2half_rn(0.f);
        *(uint4*)&g_z[node * Z_PAD]      = *(uint4*)&zh[0];
        *(uint4*)&g_z[node * Z_PAD + 8]  = *(uint4*)&zh[8];
        *(uint4*)&g_z[node * Z_PAD + 16] = *(uint4*)&zh[16];
    }
}

// ---- layer-2 aggregation of z + mean-pool: thread per 2 consecutive nodes ----
__global__ void __launch_bounds__(256) k_aggpool(const int* __restrict__ batch) {
    int gid = blockIdx.x * blockDim.x + threadIdx.x;
    int n0 = gid * 2;
    if (n0 >= N_NODES) return;

    float run[20];
#pragma unroll
    for (int o = 0; o < 20; o++) run[o] = 0.f;
    int gprev = -1;

#pragma unroll
    for (int ni = 0; ni < 2; ni++) {
        int node = n0 + ni;
        if (node >= N_NODES) break;
        float acc[20];
        // self term
        {
            uint4 u0 = *(const uint4*)&g_z[node * Z_PAD];
            uint4 u1 = *(const uint4*)&g_z[node * Z_PAD + 8];
            uint2 u2 = *(const uint2*)&g_z[node * Z_PAD + 16];
            float2 p;
            p = __half22float2(*(__half2*)&u0.x); acc[0] = p.x;  acc[1] = p.y;
            p = __half22float2(*(__half2*)&u0.y); acc[2] = p.x;  acc[3] = p.y;
            p = __half22float2(*(__half2*)&u0.z); acc[4] = p.x;  acc[5] = p.y;
            p = __half22float2(*(__half2*)&u0.w); acc[6] = p.x;  acc[7] = p.y;
            p = __half22float2(*(__half2*)&u1.x); acc[8] = p.x;  acc[9] = p.y;
            p = __half22float2(*(__half2*)&u1.y); acc[10] = p.x; acc[11] = p.y;
            p = __half22float2(*(__half2*)&u1.z); acc[12] = p.x; acc[13] = p.y;
            p = __half22float2(*(__half2*)&u1.w); acc[14] = p.x; acc[15] = p.y;
            p = __half22float2(*(__half2*)&u2.x); acc[16] = p.x; acc[17] = p.y;
            p = __half22float2(*(__half2*)&u2.y); acc[18] = p.x; acc[19] = p.y;
        }
        int rs = g_rowptr[node], re = g_rowptr[node + 1];
#pragma unroll 2
        for (int e = rs; e < re; e++) {
            int s = g_csr[e];
            uint4 u0 = *(const uint4*)&g_z[s * Z_PAD];
            uint4 u1 = *(const uint4*)&g_z[s * Z_PAD + 8];
            uint2 u2 = *(const uint2*)&g_z[s * Z_PAD + 16];
            float2 p;
            p = __half22float2(*(__half2*)&u0.x); acc[0] += p.x;  acc[1] += p.y;
            p = __half22float2(*(__half2*)&u0.y); acc[2] += p.x;  acc[3] += p.y;
            p = __half22float2(*(__half2*)&u0.z); acc[4] += p.x;  acc[5] += p.y;
            p = __half22float2(*(__half2*)&u0.w); acc[6] += p.x;  acc[7] += p.y;
            p = __half22float2(*(__half2*)&u1.x); acc[8] += p.x;  acc[9] += p.y;
            p = __half22float2(*(__half2*)&u1.y); acc[10] += p.x; acc[11] += p.y;
            p = __half22float2(*(__half2*)&u1.z); acc[12] += p.x; acc[13] += p.y;
            p = __half22float2(*(__half2*)&u1.w); acc[14] += p.x; acc[15] += p.y;
            p = __half22float2(*(__half2*)&u2.x); acc[16] += p.x; acc[17] += p.y;
            p = __half22float2(*(__half2*)&u2.y); acc[18] += p.x; acc[19] += p.y;
        }
        float di = g_dinv[node];
        int g = batch[node];
        if (g != gprev) {
            if (gprev >= 0) {
#pragma unroll
                for (int o = 0; o < 20; o++) atomicAdd(&g_q[gprev * 20 + o], run[o]);
#pragma unroll
                for (int o = 0; o < 20; o++) run[o] = 0.f;
            }
            gprev = g;
        }
#pragma unroll
        for (int o = 0; o < 20; o++) run[o] = fmaf(acc[o], di, run[o]);
    }
    if (gprev >= 0) {
#pragma unroll
        for (int o = 0; o < 20; o++) atomicAdd(&g_q[gprev * 20 + o], run[o]);
    }
}

// out[g][o] = q[g][o] / max(cnt,1) + bc[o]   (elementwise)
__global__ void k_final(float* __restrict__ out) {
    int idx = blockIdx.x * blockDim.x + threadIdx.x;
    if (idx >= NUM_GRAPHS * F_OUT) return;
    int g = idx / F_OUT, o = idx - g * F_OUT;
    float inv = 1.f / fmaxf(g_gcnt[g], 1.f);
    out[idx] = g_q[g * 20 + o] * inv + g_bc[o];
}

// ---------------- launch ----------------
extern "C" void kernel_launch(void* const* d_in, const int* in_sizes, int n_in,
                              void* d_out, int out_size) {
    const float* x    = (const float*)d_in[0];
    const int*   esrc = (const int*)d_in[1];
    const int*   edst = (const int*)d_in[2];
    const int*   batch= (const int*)d_in[3];
    const float* W1   = (const float*)d_in[4];
    const float* b1   = (const float*)d_in[5];
    const float* W2   = (const float*)d_in[6];
    const float* b2   = (const float*)d_in[7];
    const float* Wlin = (const float*)d_in[8];
    const float* blin = (const float*)d_in[9];
    float* out = (float*)d_out;

    k_init<<<512, 256>>>(W2, b2, Wlin, blin);
    k_count<<<512, 256>>>(edst, batch);
    k_scan1<<<SCAN_NBLK, 1024>>>();
    k_scan23<<<(N_NODES + 255) / 256, 256>>>();
    k_fill<<<1024, 256>>>(esrc, edst, x);
    k_layer1<<<(N_NODES + 127) / 128, 128>>>(W1, b1);
    k_aggpool<<<(N_NODES / 2 + 255) / 256, 256>>>(batch);
    k_final<<<(NUM_GRAPHS * F_OUT + 255) / 256, 256>>>(out);
}

// round 10
// speedup vs baseline: 1.4272x; 1.4272x over previous
#include <cuda_runtime.h>
#include <cuda_fp16.h>

#define N_NODES 100000
#define N_EDGES 1600000
#define NUM_GRAPHS 4096
#define HID 128
#define F_IN 11
#define F_PAD 12
#define F_OUT 19
#define Z_PAD 32                 // halves per z row (64B, sector-aligned)

#define SCAN_CHUNK 2048
#define SCAN_NBLK ((N_NODES + SCAN_CHUNK - 1) / SCAN_CHUNK)   // 49

// ---------------- scratch (static device globals; no allocation) ----------------
__device__ int    g_cnt[N_NODES];
__device__ int    g_fill[N_NODES];
__device__ float  g_dinv[N_NODES];
__device__ int    g_rowptr[N_NODES + 1];
__device__ int    g_csr[N_EDGES];                  // src only
__device__ float  g_x12[N_NODES * F_PAD];          // x * dinv, padded to 12
__device__ __half g_z[(N_NODES + 1) * Z_PAD];      // z = h1' @ Wc, fp16; last row = 0 sentinel
__device__ float  g_q[NUM_GRAPHS * Z_PAD];         // pooled z
__device__ float  g_gcnt[NUM_GRAPHS];
__device__ float  g_Wc[HID * F_OUT];
__device__ float  g_bc[F_OUT];
__device__ int    g_bsum[64];

typedef unsigned long long ull;
__device__ __forceinline__ ull fma2(ull a, ull b, ull c) {
    ull d;
    asm("fma.rn.f32x2 %0, %1, %2, %3;" : "=l"(d) : "l"(a), "l"(b), "l"(c));
    return d;
}
__device__ __forceinline__ ull pack2(float lo, float hi) {
    ull d;
    asm("mov.b64 %0, {%1, %2};" : "=l"(d) : "f"(lo), "f"(hi));
    return d;
}
__device__ __forceinline__ void unpack2(ull v, float& lo, float& hi) {
    asm("mov.b64 {%0, %1}, %2;" : "=f"(lo), "=f"(hi) : "l"(v));
}

// ---------------- kernels ----------------

// init: zero counters/accumulators + sentinel z row, precompute Wc/bc
__global__ void k_init(const float* __restrict__ W2, const float* __restrict__ b2,
                       const float* __restrict__ Wlin, const float* __restrict__ blin) {
    int i = blockIdx.x * blockDim.x + threadIdx.x;
    int stride = gridDim.x * blockDim.x;
    for (int j = i; j < N_NODES; j += stride) { g_cnt[j] = 0; g_fill[j] = 0; }
    for (int j = i; j < NUM_GRAPHS * Z_PAD; j += stride) g_q[j] = 0.f;
    for (int j = i; j < NUM_GRAPHS; j += stride) g_gcnt[j] = 0.f;
    for (int j = i; j < Z_PAD; j += stride)
        g_z[N_NODES * Z_PAD + j] = __float2half_rn(0.f);   // sentinel row
    for (int j = i; j < HID * F_OUT + F_OUT; j += stride) {
        if (j < HID * F_OUT) {
            int k = j / F_OUT, o = j - k * F_OUT;
            float s = 0.f;
#pragma unroll 8
            for (int m = 0; m < HID; m++) s = fmaf(W2[k * HID + m], Wlin[m * F_OUT + o], s);
            g_Wc[j] = s;
        } else {
            int o = j - HID * F_OUT;
            float s = blin[o];
#pragma unroll 8
            for (int m = 0; m < HID; m++) s = fmaf(b2[m], Wlin[m * F_OUT + o], s);
            g_bc[o] = s;
        }
    }
}

// edge in-degree count + per-graph node count (int4 vectorized)
__global__ void k_count(const int* __restrict__ dst, const int* __restrict__ batch) {
    int i = blockIdx.x * blockDim.x + threadIdx.x;
    int stride = gridDim.x * blockDim.x;
    const int4* dst4 = (const int4*)dst;
    for (int e = i; e < N_EDGES / 4; e += stride) {
        int4 d = dst4[e];
        atomicAdd(&g_cnt[d.x], 1);
        atomicAdd(&g_cnt[d.y], 1);
        atomicAdd(&g_cnt[d.z], 1);
        atomicAdd(&g_cnt[d.w], 1);
    }
    const int4* b4 = (const int4*)batch;
    for (int n = i; n < N_NODES / 4; n += stride) {
        int4 b = b4[n];
        if (b.x == b.w) {
            atomicAdd(&g_gcnt[b.x], 4.f);
        } else {
            atomicAdd(&g_gcnt[b.x], 1.f);
            atomicAdd(&g_gcnt[b.y], 1.f);
            atomicAdd(&g_gcnt[b.z], 1.f);
            atomicAdd(&g_gcnt[b.w], 1.f);
        }
    }
}

// ---- scan phase 1 (+ dinv fused) ----
__global__ void k_scan1() {
    __shared__ int sm[1024];
    int t = threadIdx.x;
    int base = blockIdx.x * SCAN_CHUNK;
    int i0 = base + 2 * t, i1 = i0 + 1;
    int v0 = (i0 < N_NODES) ? g_cnt[i0] : 0;
    int v1 = (i1 < N_NODES) ? g_cnt[i1] : 0;
    if (i0 < N_NODES) g_dinv[i0] = rsqrtf((float)(v0 + 1));
    if (i1 < N_NODES) g_dinv[i1] = rsqrtf((float)(v1 + 1));
    int s = v0 + v1;
    sm[t] = s;
    __syncthreads();
    for (int off = 1; off < 1024; off <<= 1) {
        int add = (t >= off) ? sm[t - off] : 0;
        __syncthreads();
        sm[t] += add;
        __syncthreads();
    }
    int excl = sm[t] - s;
    if (i0 < N_NODES) g_rowptr[i0] = excl;
    if (i1 < N_NODES) g_rowptr[i1] = excl + v0;
    if (t == 1023) g_bsum[blockIdx.x] = sm[t];
}

// ---- scan phases 2+3 merged ----
__global__ void k_scan23() {
    __shared__ int sm[64];
    int t = threadIdx.x;
    if (t < 64) sm[t] = (t < SCAN_NBLK) ? g_bsum[t] : 0;
    __syncthreads();
    if (t == 0) {
        int run = 0;
#pragma unroll
        for (int j = 0; j < SCAN_NBLK; j++) { int v = sm[j]; sm[j] = run; run += v; }
    }
    __syncthreads();
    int i = blockIdx.x * blockDim.x + t;
    if (i < N_NODES) g_rowptr[i] += sm[i >> 11];
    if (i == 0) g_rowptr[N_NODES] = N_EDGES;
}

// CSR fill (src only, int4 reads) + build x12 = x * dinv (padded)
__global__ void k_fill(const int* __restrict__ src, const int* __restrict__ dst,
                       const float* __restrict__ x) {
    int i = blockIdx.x * blockDim.x + threadIdx.x;
    int stride = gridDim.x * blockDim.x;
    const int4* src4 = (const int4*)src;
    const int4* dst4 = (const int4*)dst;
    for (int e = i; e < N_EDGES / 4; e += stride) {
        int4 s = src4[e];
        int4 d = dst4[e];
        g_csr[g_rowptr[d.x] + atomicAdd(&g_fill[d.x], 1)] = s.x;
        g_csr[g_rowptr[d.y] + atomicAdd(&g_fill[d.y], 1)] = s.y;
        g_csr[g_rowptr[d.z] + atomicAdd(&g_fill[d.z], 1)] = s.z;
        g_csr[g_rowptr[d.w] + atomicAdd(&g_fill[d.w], 1)] = s.w;
    }
    for (int n = i; n < N_NODES; n += stride) {
        float di = g_dinv[n];
        float r[F_PAD];
#pragma unroll
        for (int f = 0; f < F_IN; f++) r[f] = x[n * F_IN + f] * di;
        r[11] = 0.f;
        *(float4*)&g_x12[n * F_PAD]     = make_float4(r[0], r[1], r[2],  r[3]);
        *(float4*)&g_x12[n * F_PAD + 4] = make_float4(r[4], r[5], r[6],  r[7]);
        *(float4*)&g_x12[n * F_PAD + 8] = make_float4(r[8], r[9], r[10], r[11]);
    }
}

// ---- fused layer 1: aggregate -> GEMM1 -> relu*dinv (smem fp16) -> z = h1' @ Wc -> g_z ----
__global__ void __launch_bounds__(128) k_layer1(const float* __restrict__ W1,
                                                const float* __restrict__ b1) {
    __shared__ float  sw[F_IN][HID];
    __shared__ float  sb[HID];
    __shared__ float  sa[128][13];
    __shared__ float  sdi[128];
    __shared__ __half sh1[128][130];   // 260B row stride -> conflict-free column access
    __shared__ ull    swc[64][F_OUT];  // (Wc[2k][o], Wc[2k+1][o]) f32 pairs
    int tid = threadIdx.x;
    for (int j = tid; j < F_IN * HID; j += 128) sw[j / HID][j % HID] = W1[j];
    for (int j = tid; j < HID; j += 128) sb[j] = b1[j];
    for (int j = tid; j < 64 * F_OUT; j += 128) {
        int k2 = j / F_OUT, o = j - k2 * F_OUT;
        swc[k2][o] = pack2(g_Wc[(2 * k2) * F_OUT + o], g_Wc[(2 * k2 + 1) * F_OUT + o]);
    }

    // phase 1: per-thread aggregation of pre-scaled x
    int node = blockIdx.x * 128 + tid;
    if (node < N_NODES) {
        float di = g_dinv[node];
        sdi[tid] = di;
        float4 a0 = *(const float4*)&g_x12[node * F_PAD];
        float4 a1 = *(const float4*)&g_x12[node * F_PAD + 4];
        float4 a2 = *(const float4*)&g_x12[node * F_PAD + 8];
        int rs = g_rowptr[node], re = g_rowptr[node + 1];
#pragma unroll 2
        for (int e = rs; e < re; e++) {
            int s = g_csr[e];
            float4 x0 = *(const float4*)&g_x12[s * F_PAD];
            float4 x1 = *(const float4*)&g_x12[s * F_PAD + 4];
            float4 x2 = *(const float4*)&g_x12[s * F_PAD + 8];
            a0.x += x0.x; a0.y += x0.y; a0.z += x0.z; a0.w += x0.w;
            a1.x += x1.x; a1.y += x1.y; a1.z += x1.z; a1.w += x1.w;
            a2.x += x2.x; a2.y += x2.y; a2.z += x2.z;
        }
        sa[tid][0] = a0.x * di; sa[tid][1] = a0.y * di; sa[tid][2]  = a0.z * di; sa[tid][3] = a0.w * di;
        sa[tid][4] = a1.x * di; sa[tid][5] = a1.y * di; sa[tid][6]  = a1.z * di; sa[tid][7] = a1.w * di;
        sa[tid][8] = a2.x * di; sa[tid][9] = a2.y * di; sa[tid][10] = a2.z * di;
    }
    __syncthreads();

    // GEMM1: warp wi computes nodes wi*32..+31; lane l -> features 4l..4l+3; h1' -> sh1 fp16
    {
        int wi = tid >> 5, l = tid & 31;
        int f = l * 4;
        float4 bias = *(const float4*)&sb[f];
#pragma unroll 4
        for (int i = 0; i < 32; i++) {
            int nn = wi * 32 + i;
            int nd = blockIdx.x * 128 + nn;
            if (nd >= N_NODES) break;
            float4 acc = bias;
#pragma unroll
            for (int k = 0; k < F_IN; k++) {
                float a = sa[nn][k];
                float4 w = *(const float4*)&sw[k][f];
                acc.x = fmaf(a, w.x, acc.x);
                acc.y = fmaf(a, w.y, acc.y);
                acc.z = fmaf(a, w.z, acc.z);
                acc.w = fmaf(a, w.w, acc.w);
            }
            float di = sdi[nn];
            sh1[nn][f]     = __float2half_rn(fmaxf(acc.x, 0.f) * di);
            sh1[nn][f + 1] = __float2half_rn(fmaxf(acc.y, 0.f) * di);
            sh1[nn][f + 2] = __float2half_rn(fmaxf(acc.z, 0.f) * di);
            sh1[nn][f + 3] = __float2half_rn(fmaxf(acc.w, 0.f) * di);
        }
    }
    __syncthreads();

    // phase 2: z[node] = sh1[node] @ Wc  (f32x2, Wc broadcast from smem)
    if (node < N_NODES) {
        ull acc[F_OUT];
#pragma unroll
        for (int o = 0; o < F_OUT; o++) acc[o] = 0ull;
        for (int k2 = 0; k2 < 64; k2++) {
            float2 af = __half22float2(*(__half2*)&sh1[tid][2 * k2]);
            ull aa = pack2(af.x, af.y);
#pragma unroll
            for (int o = 0; o < F_OUT; o++) acc[o] = fma2(aa, swc[k2][o], acc[o]);
        }
        __half zh[Z_PAD];
#pragma unroll
        for (int o = 0; o < F_OUT; o++) {
            float lo, hi;
            unpack2(acc[o], lo, hi);
            zh[o] = __float2half_rn(lo + hi);
        }
#pragma unroll
        for (int o = F_OUT; o < Z_PAD; o++) zh[o] = __float2half_rn(0.f);
        *(uint4*)&g_z[node * Z_PAD]      = *(uint4*)&zh[0];
        *(uint4*)&g_z[node * Z_PAD + 8]  = *(uint4*)&zh[8];
        *(uint4*)&g_z[node * Z_PAD + 16] = *(uint4*)&zh[16];
        *(uint4*)&g_z[node * Z_PAD + 24] = *(uint4*)&zh[24];
    }
}

// ---- layer-2 aggregation of z + mean-pool (R8 warp structure, 64B z rows) ----
// warp per 8 nodes; 16-lane groups on even/odd edges; lane owns 2 z-halves
__global__ void __launch_bounds__(256) k_aggpool(const int* __restrict__ batch) {
    int tid = threadIdx.x;
    int wi = tid >> 5, l = tid & 31;
    int group = l >> 4;             // 0: even edges, 1: odd edges
    int fh = (l & 15) * 2;          // this lane's 2 z features
    int node0 = blockIdx.x * 64 + wi * 8;

    int gprev = -1;
    float run = 0.f;
    int fout = fh + group;          // after combine, lane atomics 1 feature

#pragma unroll 1
    for (int i = 0; i < 8; i++) {
        int node = node0 + i;
        if (node >= N_NODES) break;
        float a0, a1;
        {
            // self term (group 0 only; group 1 contributes 0, fixed at combine)
            unsigned u = *(const unsigned*)&g_z[node * Z_PAD + fh];
            float2 p = __half22float2(*(__half2*)&u);
            float sw0 = (group == 0) ? 1.f : 0.f;
            a0 = p.x * sw0; a1 = p.y * sw0;
        }
        int rs = g_rowptr[node], re = g_rowptr[node + 1];
        for (int e0 = rs; e0 < re; e0 += 32) {
            int ec = min(32, re - e0);
            int cs = (e0 + l < re) ? g_csr[e0 + l] : N_NODES;   // sentinel -> zero row
            int jmax = (ec + 1) >> 1;
#pragma unroll 4
            for (int j = 0; j < jmax; j++) {
                int sl = 2 * j + group;
                int s = __shfl_sync(0xffffffffu, cs, sl);
                unsigned u = *(const unsigned*)&g_z[s * Z_PAD + fh];
                float2 p = __half22float2(*(__half2*)&u);
                a0 += p.x; a1 += p.y;
            }
        }
        a0 += __shfl_xor_sync(0xffffffffu, a0, 16);
        a1 += __shfl_xor_sync(0xffffffffu, a1, 16);
        float v = (group ? a1 : a0) * g_dinv[node];

        int g = batch[node];
        if (g != gprev) {
            if (gprev >= 0 && fout < F_OUT)
                atomicAdd(&g_q[gprev * Z_PAD + fout], run);
            gprev = g; run = 0.f;
        }
        run += v;
    }
    if (gprev >= 0 && fout < F_OUT)
        atomicAdd(&g_q[gprev * Z_PAD + fout], run);
}

// out[g][o] = q[g][o] / max(cnt,1) + bc[o]   (elementwise)
__global__ void k_final(float* __restrict__ out) {
    int idx = blockIdx.x * blockDim.x + threadIdx.x;
    if (idx >= NUM_GRAPHS * F_OUT) return;
    int g = idx / F_OUT, o = idx - g * F_OUT;
    float inv = 1.f / fmaxf(g_gcnt[g], 1.f);
    out[idx] = g_q[g * Z_PAD + o] * inv + g_bc[o];
}

// ---------------- launch ----------------
extern "C" void kernel_launch(void* const* d_in, const int* in_sizes, int n_in,
                              void* d_out, int out_size) {
    const float* x    = (const float*)d_in[0];
    const int*   esrc = (const int*)d_in[1];
    const int*   edst = (const int*)d_in[2];
    const int*   batch= (const int*)d_in[3];
    const float* W1   = (const float*)d_in[4];
    const float* b1   = (const float*)d_in[5];
    const float* W2   = (const float*)d_in[6];
    const float* b2   = (const float*)d_in[7];
    const float* Wlin = (const float*)d_in[8];
    const float* blin = (const float*)d_in[9];
    float* out = (float*)d_out;

    k_init<<<512, 256>>>(W2, b2, Wlin, blin);
    k_count<<<512, 256>>>(edst, batch);
    k_scan1<<<SCAN_NBLK, 1024>>>();
    k_scan23<<<(N_NODES + 255) / 256, 256>>>();
    k_fill<<<1024, 256>>>(esrc, edst, x);
    k_layer1<<<(N_NODES + 127) / 128, 128>>>(W1, b1);
    k_aggpool<<<(N_NODES + 63) / 64, 256>>>(batch);
    k_final<<<(NUM_GRAPHS * F_OUT + 255) / 256, 256>>>(out);
}

// round 15
// speedup vs baseline: 1.5299x; 1.0719x over previous
#include <cuda_runtime.h>
#include <cuda_fp16.h>

#define N_NODES 100000
#define N_EDGES 1600000
#define NUM_GRAPHS 4096
#define HID 128
#define F_IN 11
#define F_PAD 12
#define F_OUT 19
#define Z_PAD 32                 // halves per z row (64B, sector-aligned)

#define SCAN_CHUNK 2048
#define SCAN_NBLK ((N_NODES + SCAN_CHUNK - 1) / SCAN_CHUNK)   // 49

// ---------------- scratch (static device globals; no allocation) ----------------
__device__ int    g_cnt[N_NODES];
__device__ int    g_fill[N_NODES];
__device__ float  g_dinv[N_NODES];
__device__ int    g_rowptr[N_NODES + 1];
__device__ int    g_csr[N_EDGES];                  // src only
__device__ float  g_x12[N_NODES * F_PAD];          // x * dinv, padded to 12
__device__ __half g_h1h[N_NODES * HID];            // h1' = relu(h1)*dinv, fp16
__device__ __half g_z[(N_NODES + 1) * Z_PAD];      // z = h1' @ Wc, fp16; last row = 0 sentinel
__device__ float  g_q[NUM_GRAPHS * Z_PAD];         // pooled z
__device__ float  g_gcnt[NUM_GRAPHS];
__device__ float  g_Wc[HID * F_OUT];
__device__ float  g_bc[F_OUT];
__device__ int    g_bsum[64];

typedef unsigned long long ull;
__device__ __forceinline__ ull fma2(ull a, ull b, ull c) {
    ull d;
    asm("fma.rn.f32x2 %0, %1, %2, %3;" : "=l"(d) : "l"(a), "l"(b), "l"(c));
    return d;
}
__device__ __forceinline__ ull pack2(float lo, float hi) {
    ull d;
    asm("mov.b64 %0, {%1, %2};" : "=l"(d) : "f"(lo), "f"(hi));
    return d;
}
__device__ __forceinline__ void unpack2(ull v, float& lo, float& hi) {
    asm("mov.b64 {%0, %1}, %2;" : "=f"(lo), "=f"(hi) : "l"(v));
}

// ---------------- kernels ----------------

// init: zero counters/accumulators + sentinel z row, precompute Wc/bc
__global__ void k_init(const float* __restrict__ W2, const float* __restrict__ b2,
                       const float* __restrict__ Wlin, const float* __restrict__ blin) {
    int i = blockIdx.x * blockDim.x + threadIdx.x;
    int stride = gridDim.x * blockDim.x;
    for (int j = i; j < N_NODES; j += stride) { g_cnt[j] = 0; g_fill[j] = 0; }
    for (int j = i; j < NUM_GRAPHS * Z_PAD; j += stride) g_q[j] = 0.f;
    for (int j = i; j < NUM_GRAPHS; j += stride) g_gcnt[j] = 0.f;
    for (int j = i; j < Z_PAD; j += stride)
        g_z[N_NODES * Z_PAD + j] = __float2half_rn(0.f);   // sentinel row
    for (int j = i; j < HID * F_OUT + F_OUT; j += stride) {
        if (j < HID * F_OUT) {
            int k = j / F_OUT, o = j - k * F_OUT;
            float s = 0.f;
#pragma unroll 8
            for (int m = 0; m < HID; m++) s = fmaf(W2[k * HID + m], Wlin[m * F_OUT + o], s);
            g_Wc[j] = s;
        } else {
            int o = j - HID * F_OUT;
            float s = blin[o];
#pragma unroll 8
            for (int m = 0; m < HID; m++) s = fmaf(b2[m], Wlin[m * F_OUT + o], s);
            g_bc[o] = s;
        }
    }
}

// edge in-degree count + per-graph node count (int4 vectorized)
__global__ void k_count(const int* __restrict__ dst, const int* __restrict__ batch) {
    int i = blockIdx.x * blockDim.x + threadIdx.x;
    int stride = gridDim.x * blockDim.x;
    const int4* dst4 = (const int4*)dst;
    for (int e = i; e < N_EDGES / 4; e += stride) {
        int4 d = dst4[e];
        atomicAdd(&g_cnt[d.x], 1);
        atomicAdd(&g_cnt[d.y], 1);
        atomicAdd(&g_cnt[d.z], 1);
        atomicAdd(&g_cnt[d.w], 1);
    }
    const int4* b4 = (const int4*)batch;
    for (int n = i; n < N_NODES / 4; n += stride) {
        int4 b = b4[n];
        if (b.x == b.w) {
            atomicAdd(&g_gcnt[b.x], 4.f);
        } else {
            atomicAdd(&g_gcnt[b.x], 1.f);
            atomicAdd(&g_gcnt[b.y], 1.f);
            atomicAdd(&g_gcnt[b.z], 1.f);
            atomicAdd(&g_gcnt[b.w], 1.f);
        }
    }
}

// ---- scan phase 1 (+ dinv fused) ----
__global__ void k_scan1() {
    __shared__ int sm[1024];
    int t = threadIdx.x;
    int base = blockIdx.x * SCAN_CHUNK;
    int i0 = base + 2 * t, i1 = i0 + 1;
    int v0 = (i0 < N_NODES) ? g_cnt[i0] : 0;
    int v1 = (i1 < N_NODES) ? g_cnt[i1] : 0;
    if (i0 < N_NODES) g_dinv[i0] = rsqrtf((float)(v0 + 1));
    if (i1 < N_NODES) g_dinv[i1] = rsqrtf((float)(v1 + 1));
    int s = v0 + v1;
    sm[t] = s;
    __syncthreads();
    for (int off = 1; off < 1024; off <<= 1) {
        int add = (t >= off) ? sm[t - off] : 0;
        __syncthreads();
        sm[t] += add;
        __syncthreads();
    }
    int excl = sm[t] - s;
    if (i0 < N_NODES) g_rowptr[i0] = excl;
    if (i1 < N_NODES) g_rowptr[i1] = excl + v0;
    if (t == 1023) g_bsum[blockIdx.x] = sm[t];
}

// ---- scan phases 2+3 merged ----
__global__ void k_scan23() {
    __shared__ int sm[64];
    int t = threadIdx.x;
    if (t < 64) sm[t] = (t < SCAN_NBLK) ? g_bsum[t] : 0;
    __syncthreads();
    if (t == 0) {
        int run = 0;
#pragma unroll
        for (int j = 0; j < SCAN_NBLK; j++) { int v = sm[j]; sm[j] = run; run += v; }
    }
    __syncthreads();
    int i = blockIdx.x * blockDim.x + t;
    if (i < N_NODES) g_rowptr[i] += sm[i >> 11];
    if (i == 0) g_rowptr[N_NODES] = N_EDGES;
}

// CSR fill (src only, int4 reads) + build x12 = x * dinv (padded)
__global__ void k_fill(const int* __restrict__ src, const int* __restrict__ dst,
                       const float* __restrict__ x) {
    int i = blockIdx.x * blockDim.x + threadIdx.x;
    int stride = gridDim.x * blockDim.x;
    const int4* src4 = (const int4*)src;
    const int4* dst4 = (const int4*)dst;
    for (int e = i; e < N_EDGES / 4; e += stride) {
        int4 s = src4[e];
        int4 d = dst4[e];
        g_csr[g_rowptr[d.x] + atomicAdd(&g_fill[d.x], 1)] = s.x;
        g_csr[g_rowptr[d.y] + atomicAdd(&g_fill[d.y], 1)] = s.y;
        g_csr[g_rowptr[d.z] + atomicAdd(&g_fill[d.z], 1)] = s.z;
        g_csr[g_rowptr[d.w] + atomicAdd(&g_fill[d.w], 1)] = s.w;
    }
    for (int n = i; n < N_NODES; n += stride) {
        float di = g_dinv[n];
        float r[F_PAD];
#pragma unroll
        for (int f = 0; f < F_IN; f++) r[f] = x[n * F_IN + f] * di;
        r[11] = 0.f;
        *(float4*)&g_x12[n * F_PAD]     = make_float4(r[0], r[1], r[2],  r[3]);
        *(float4*)&g_x12[n * F_PAD + 4] = make_float4(r[4], r[5], r[6],  r[7]);
        *(float4*)&g_x12[n * F_PAD + 8] = make_float4(r[8], r[9], r[10], r[11]);
    }
}

// ---- layer 1 (R8 structure): aggregate x' -> smem -> warp GEMM -> relu*dinv -> fp16 gmem ----
__global__ void __launch_bounds__(128) k_layer1(const float* __restrict__ W1,
                                                const float* __restrict__ b1) {
    __shared__ float sw[F_IN][HID];
    __shared__ float sb[HID];
    __shared__ float sa[128][13];
    __shared__ float sdi[128];
    int tid = threadIdx.x;
    for (int j = tid; j < F_IN * HID; j += 128) sw[j / HID][j % HID] = W1[j];
    for (int j = tid; j < HID; j += 128) sb[j] = b1[j];

    int node = blockIdx.x * 128 + tid;
    if (node < N_NODES) {
        float di = g_dinv[node];
        sdi[tid] = di;
        float4 a0 = *(const float4*)&g_x12[node * F_PAD];
        float4 a1 = *(const float4*)&g_x12[node * F_PAD + 4];
        float4 a2 = *(const float4*)&g_x12[node * F_PAD + 8];
        int rs = g_rowptr[node], re = g_rowptr[node + 1];
#pragma unroll 2
        for (int e = rs; e < re; e++) {
            int s = g_csr[e];
            float4 x0 = *(const float4*)&g_x12[s * F_PAD];
            float4 x1 = *(const float4*)&g_x12[s * F_PAD + 4];
            float4 x2 = *(const float4*)&g_x12[s * F_PAD + 8];
            a0.x += x0.x; a0.y += x0.y; a0.z += x0.z; a0.w += x0.w;
            a1.x += x1.x; a1.y += x1.y; a1.z += x1.z; a1.w += x1.w;
            a2.x += x2.x; a2.y += x2.y; a2.z += x2.z;
        }
        sa[tid][0] = a0.x * di; sa[tid][1] = a0.y * di; sa[tid][2]  = a0.z * di; sa[tid][3] = a0.w * di;
        sa[tid][4] = a1.x * di; sa[tid][5] = a1.y * di; sa[tid][6]  = a1.z * di; sa[tid][7] = a1.w * di;
        sa[tid][8] = a2.x * di; sa[tid][9] = a2.y * di; sa[tid][10] = a2.z * di;
    }
    __syncthreads();

    int wi = tid >> 5, l = tid & 31;
    int f = l * 4;
    float4 bias = *(const float4*)&sb[f];
#pragma unroll 4
    for (int i = 0; i < 32; i++) {
        int nn = wi * 32 + i;
        int nd = blockIdx.x * 128 + nn;
        if (nd >= N_NODES) break;
        float4 acc = bias;
#pragma unroll
        for (int k = 0; k < F_IN; k++) {
            float a = sa[nn][k];
            float4 w = *(const float4*)&sw[k][f];
            acc.x = fmaf(a, w.x, acc.x);
            acc.y = fmaf(a, w.y, acc.y);
            acc.z = fmaf(a, w.z, acc.z);
            acc.w = fmaf(a, w.w, acc.w);
        }
        float di = sdi[nn];
        uint2 st;
        *(__half2*)&st.x = __floats2half2_rn(fmaxf(acc.x, 0.f) * di, fmaxf(acc.y, 0.f) * di);
        *(__half2*)&st.y = __floats2half2_rn(fmaxf(acc.z, 0.f) * di, fmaxf(acc.w, 0.f) * di);
        *(uint2*)&g_h1h[nd * HID + f] = st;
    }
}

// ---- z projection: z[node] = h1'[node] @ Wc (thread-per-node, small smem, f32x2) ----
__global__ void __launch_bounds__(256) k_zproj() {
    __shared__ ull swc[64][F_OUT];   // (Wc[2k][o], Wc[2k+1][o]) f32 pairs
    int tid = threadIdx.x;
    for (int j = tid; j < 64 * F_OUT; j += 256) {
        int k2 = j / F_OUT, o = j - k2 * F_OUT;
        swc[k2][o] = pack2(g_Wc[(2 * k2) * F_OUT + o], g_Wc[(2 * k2 + 1) * F_OUT + o]);
    }
    __syncthreads();
    int node = blockIdx.x * 256 + tid;
    if (node >= N_NODES) return;

    ull acc[F_OUT];
#pragma unroll
    for (int o = 0; o < F_OUT; o++) acc[o] = 0ull;
#pragma unroll 2
    for (int kb = 0; kb < 16; kb++) {
        uint4 u = *(const uint4*)&g_h1h[node * HID + kb * 8];
        unsigned uu[4] = {u.x, u.y, u.z, u.w};
#pragma unroll
        for (int q = 0; q < 4; q++) {
            float2 af = __half22float2(*(__half2*)&uu[q]);
            ull aa = pack2(af.x, af.y);
            int k2 = kb * 4 + q;
#pragma unroll
            for (int o = 0; o < F_OUT; o++) acc[o] = fma2(aa, swc[k2][o], acc[o]);
        }
    }
    __half zh[Z_PAD];
#pragma unroll
    for (int o = 0; o < F_OUT; o++) {
        float lo, hi;
        unpack2(acc[o], lo, hi);
        zh[o] = __float2half_rn(lo + hi);
    }
#pragma unroll
    for (int o = F_OUT; o < Z_PAD; o++) zh[o] = __float2half_rn(0.f);
    *(uint4*)&g_z[node * Z_PAD]      = *(uint4*)&zh[0];
    *(uint4*)&g_z[node * Z_PAD + 8]  = *(uint4*)&zh[8];
    *(uint4*)&g_z[node * Z_PAD + 16] = *(uint4*)&zh[16];
    *(uint4*)&g_z[node * Z_PAD + 24] = *(uint4*)&zh[24];
}

// ---- layer-2 aggregation of z + mean-pool (warp per 8 nodes, 64B z rows) ----
__global__ void __launch_bounds__(256) k_aggpool(const int* __restrict__ batch) {
    int tid = threadIdx.x;
    int wi = tid >> 5, l = tid & 31;
    int group = l >> 4;             // 0: even edges, 1: odd edges
    int fh = (l & 15) * 2;          // this lane's 2 z features
    int node0 = blockIdx.x * 64 + wi * 8;

    int gprev = -1;
    float run = 0.f;
    int fout = fh + group;          // after combine, lane atomics 1 feature

#pragma unroll 1
    for (int i = 0; i < 8; i++) {
        int node = node0 + i;
        if (node >= N_NODES) break;
        float a0, a1;
        {
            unsigned u = *(const unsigned*)&g_z[node * Z_PAD + fh];
            float2 p = __half22float2(*(__half2*)&u);
            float sw0 = (group == 0) ? 1.f : 0.f;
            a0 = p.x * sw0; a1 = p.y * sw0;
        }
        int rs = g_rowptr[node], re = g_rowptr[node + 1];
        for (int e0 = rs; e0 < re; e0 += 32) {
            int ec = min(32, re - e0);
            int cs = (e0 + l < re) ? g_csr[e0 + l] : N_NODES;   // sentinel -> zero row
            int jmax = (ec + 1) >> 1;
#pragma unroll 4
            for (int j = 0; j < jmax; j++) {
                int sl = 2 * j + group;
                int s = __shfl_sync(0xffffffffu, cs, sl);
                unsigned u = *(const unsigned*)&g_z[s * Z_PAD + fh];
                float2 p = __half22float2(*(__half2*)&u);
                a0 += p.x; a1 += p.y;
            }
        }
        a0 += __shfl_xor_sync(0xffffffffu, a0, 16);
        a1 += __shfl_xor_sync(0xffffffffu, a1, 16);
        float v = (group ? a1 : a0) * g_dinv[node];

        int g = batch[node];
        if (g != gprev) {
            if (gprev >= 0 && fout < F_OUT)
                atomicAdd(&g_q[gprev * Z_PAD + fout], run);
            gprev = g; run = 0.f;
        }
        run += v;
    }
    if (gprev >= 0 && fout < F_OUT)
        atomicAdd(&g_q[gprev * Z_PAD + fout], run);
}

// out[g][o] = q[g][o] / max(cnt,1) + bc[o]   (elementwise)
__global__ void k_final(float* __restrict__ out) {
    int idx = blockIdx.x * blockDim.x + threadIdx.x;
    if (idx >= NUM_GRAPHS * F_OUT) return;
    int g = idx / F_OUT, o = idx - g * F_OUT;
    float inv = 1.f / fmaxf(g_gcnt[g], 1.f);
    out[idx] = g_q[g * Z_PAD + o] * inv + g_bc[o];
}

// ---------------- launch ----------------
extern "C" void kernel_launch(void* const* d_in, const int* in_sizes, int n_in,
                              void* d_out, int out_size) {
    const float* x    = (const float*)d_in[0];
    const int*   esrc = (const int*)d_in[1];
    const int*   edst = (const int*)d_in[2];
    const int*   batch= (const int*)d_in[3];
    const float* W1   = (const float*)d_in[4];
    const float* b1   = (const float*)d_in[5];
    const float* W2   = (const float*)d_in[6];
    const float* b2   = (const float*)d_in[7];
    const float* Wlin = (const float*)d_in[8];
    const float* blin = (const float*)d_in[9];
    float* out = (float*)d_out;

    k_init<<<512, 256>>>(W2, b2, Wlin, blin);
    k_count<<<512, 256>>>(edst, batch);
    k_scan1<<<SCAN_NBLK, 1024>>>();
    k_scan23<<<(N_NODES + 255) / 256, 256>>>();
    k_fill<<<1024, 256>>>(esrc, edst, x);
    k_layer1<<<(N_NODES + 127) / 128, 128>>>(W1, b1);
    k_zproj<<<(N_NODES + 255) / 256, 256>>>();
    k_aggpool<<<(N_NODES + 63) / 64, 256>>>(batch);
    k_final<<<(NUM_GRAPHS * F_OUT + 255) / 256, 256>>>(out);
}

// round 16
// speedup vs baseline: 1.6732x; 1.0937x over previous
#include <cuda_runtime.h>
#include <cuda_fp16.h>

#define N_NODES 100000
#define N_EDGES 1600000
#define NUM_GRAPHS 4096
#define HID 128
#define F_IN 11
#define F_PAD 12
#define F_OUT 19

#define SCAN_CHUNK 2048
#define SCAN_NBLK ((N_NODES + SCAN_CHUNK - 1) / SCAN_CHUNK)   // 49

// ---------------- scratch (static device globals; no allocation) ----------------
// Invariant: g_cnt, g_fill, g_q, g_gcnt are ZERO at kernel_launch entry.
// (zero-initialized at module load; k_final re-zeroes them at the end of every call)
__device__ int    g_cnt[N_NODES];
__device__ int    g_fill[N_NODES];
__device__ float  g_dinv[N_NODES];
__device__ int    g_rowptr[N_NODES + 1];
__device__ int    g_csr[N_EDGES];                  // src only
__device__ float  g_x12[N_NODES * F_PAD];          // x * dinv, padded to 12
__device__ __half g_h1h[(N_NODES + 1) * HID];      // h1' = relu(h1)*dinv; last row stays 0 (sentinel, never written)
__device__ float  g_q[NUM_GRAPHS * HID];           // pooled aggregated h1'
__device__ float  g_gcnt[NUM_GRAPHS];
__device__ float  g_Wc[HID * F_OUT];               // W2 @ Wlin
__device__ float  g_bc[F_OUT];                     // b2 @ Wlin + blin
__device__ int    g_bsum[64];

// ---------------- kernels ----------------

// edge in-degree count + per-graph node count (int4 vectorized); cnt/gcnt pre-zeroed
__global__ void k_count(const int* __restrict__ dst, const int* __restrict__ batch) {
    int i = blockIdx.x * blockDim.x + threadIdx.x;
    int stride = gridDim.x * blockDim.x;
    const int4* dst4 = (const int4*)dst;
    for (int e = i; e < N_EDGES / 4; e += stride) {
        int4 d = dst4[e];
        atomicAdd(&g_cnt[d.x], 1);
        atomicAdd(&g_cnt[d.y], 1);
        atomicAdd(&g_cnt[d.z], 1);
        atomicAdd(&g_cnt[d.w], 1);
    }
    const int4* b4 = (const int4*)batch;
    for (int n = i; n < N_NODES / 4; n += stride) {
        int4 b = b4[n];
        if (b.x == b.w) {
            atomicAdd(&g_gcnt[b.x], 4.f);
        } else {
            atomicAdd(&g_gcnt[b.x], 1.f);
            atomicAdd(&g_gcnt[b.y], 1.f);
            atomicAdd(&g_gcnt[b.z], 1.f);
            atomicAdd(&g_gcnt[b.w], 1.f);
        }
    }
}

// ---- scan phase 1 (+ dinv fused) ----
__global__ void k_scan1() {
    __shared__ int sm[1024];
    int t = threadIdx.x;
    int base = blockIdx.x * SCAN_CHUNK;
    int i0 = base + 2 * t, i1 = i0 + 1;
    int v0 = (i0 < N_NODES) ? g_cnt[i0] : 0;
    int v1 = (i1 < N_NODES) ? g_cnt[i1] : 0;
    if (i0 < N_NODES) g_dinv[i0] = rsqrtf((float)(v0 + 1));
    if (i1 < N_NODES) g_dinv[i1] = rsqrtf((float)(v1 + 1));
    int s = v0 + v1;
    sm[t] = s;
    __syncthreads();
    for (int off = 1; off < 1024; off <<= 1) {
        int add = (t >= off) ? sm[t - off] : 0;
        __syncthreads();
        sm[t] += add;
        __syncthreads();
    }
    int excl = sm[t] - s;
    if (i0 < N_NODES) g_rowptr[i0] = excl;
    if (i1 < N_NODES) g_rowptr[i1] = excl + v0;
    if (t == 1023) g_bsum[blockIdx.x] = sm[t];
}

// ---- scan fixup + x12 = x*dinv build + Wc/bc precompute ----
__global__ void k_scan23(const float* __restrict__ x,
                         const float* __restrict__ W2, const float* __restrict__ b2,
                         const float* __restrict__ Wlin, const float* __restrict__ blin) {
    __shared__ int sm[64];
    int t = threadIdx.x;
    if (t < 64) sm[t] = (t < SCAN_NBLK) ? g_bsum[t] : 0;
    __syncthreads();
    if (t == 0) {
        int run = 0;
#pragma unroll
        for (int j = 0; j < SCAN_NBLK; j++) { int v = sm[j]; sm[j] = run; run += v; }
    }
    __syncthreads();
    int i = blockIdx.x * blockDim.x + t;
    if (i < N_NODES) g_rowptr[i] += sm[i >> 11];
    if (i == 0) g_rowptr[N_NODES] = N_EDGES;

    int stride = gridDim.x * blockDim.x;
    // x12 = x * dinv, padded to 12 floats/row
    for (int n = i; n < N_NODES; n += stride) {
        float di = g_dinv[n];
        float r[F_PAD];
#pragma unroll
        for (int f = 0; f < F_IN; f++) r[f] = x[n * F_IN + f] * di;
        r[11] = 0.f;
        *(float4*)&g_x12[n * F_PAD]     = make_float4(r[0], r[1], r[2],  r[3]);
        *(float4*)&g_x12[n * F_PAD + 4] = make_float4(r[4], r[5], r[6],  r[7]);
        *(float4*)&g_x12[n * F_PAD + 8] = make_float4(r[8], r[9], r[10], r[11]);
    }
    // Wc = W2 @ Wlin ; bc = b2 @ Wlin + blin
    for (int j = i; j < HID * F_OUT + F_OUT; j += stride) {
        if (j < HID * F_OUT) {
            int k = j / F_OUT, o = j - k * F_OUT;
            float s = 0.f;
#pragma unroll 8
            for (int m = 0; m < HID; m++) s = fmaf(W2[k * HID + m], Wlin[m * F_OUT + o], s);
            g_Wc[j] = s;
        } else {
            int o = j - HID * F_OUT;
            float s = blin[o];
#pragma unroll 8
            for (int m = 0; m < HID; m++) s = fmaf(b2[m], Wlin[m * F_OUT + o], s);
            g_bc[o] = s;
        }
    }
}

// CSR fill (src only, int4 reads); fill cursors pre-zeroed
__global__ void k_fill(const int* __restrict__ src, const int* __restrict__ dst) {
    int i = blockIdx.x * blockDim.x + threadIdx.x;
    int stride = gridDim.x * blockDim.x;
    const int4* src4 = (const int4*)src;
    const int4* dst4 = (const int4*)dst;
    for (int e = i; e < N_EDGES / 4; e += stride) {
        int4 s = src4[e];
        int4 d = dst4[e];
        g_csr[g_rowptr[d.x] + atomicAdd(&g_fill[d.x], 1)] = s.x;
        g_csr[g_rowptr[d.y] + atomicAdd(&g_fill[d.y], 1)] = s.y;
        g_csr[g_rowptr[d.z] + atomicAdd(&g_fill[d.z], 1)] = s.z;
        g_csr[g_rowptr[d.w] + atomicAdd(&g_fill[d.w], 1)] = s.w;
    }
}

// ---- layer 1: aggregate x' -> smem -> warp GEMM -> relu*dinv -> fp16 gmem ----
__global__ void __launch_bounds__(128) k_layer1(const float* __restrict__ W1,
                                                const float* __restrict__ b1) {
    __shared__ float sw[F_IN][HID];
    __shared__ float sb[HID];
    __shared__ float sa[128][13];
    __shared__ float sdi[128];
    int tid = threadIdx.x;
    for (int j = tid; j < F_IN * HID; j += 128) sw[j / HID][j % HID] = W1[j];
    for (int j = tid; j < HID; j += 128) sb[j] = b1[j];

    int node = blockIdx.x * 128 + tid;
    if (node < N_NODES) {
        float di = g_dinv[node];
        sdi[tid] = di;
        float4 a0 = *(const float4*)&g_x12[node * F_PAD];
        float4 a1 = *(const float4*)&g_x12[node * F_PAD + 4];
        float4 a2 = *(const float4*)&g_x12[node * F_PAD + 8];
        int rs = g_rowptr[node], re = g_rowptr[node + 1];
#pragma unroll 2
        for (int e = rs; e < re; e++) {
            int s = g_csr[e];
            float4 x0 = *(const float4*)&g_x12[s * F_PAD];
            float4 x1 = *(const float4*)&g_x12[s * F_PAD + 4];
            float4 x2 = *(const float4*)&g_x12[s * F_PAD + 8];
            a0.x += x0.x; a0.y += x0.y; a0.z += x0.z; a0.w += x0.w;
            a1.x += x1.x; a1.y += x1.y; a1.z += x1.z; a1.w += x1.w;
            a2.x += x2.x; a2.y += x2.y; a2.z += x2.z;
        }
        sa[tid][0] = a0.x * di; sa[tid][1] = a0.y * di; sa[tid][2]  = a0.z * di; sa[tid][3] = a0.w * di;
        sa[tid][4] = a1.x * di; sa[tid][5] = a1.y * di; sa[tid][6]  = a1.z * di; sa[tid][7] = a1.w * di;
        sa[tid][8] = a2.x * di; sa[tid][9] = a2.y * di; sa[tid][10] = a2.z * di;
    }
    __syncthreads();

    int wi = tid >> 5, l = tid & 31;
    int f = l * 4;
    float4 bias = *(const float4*)&sb[f];
#pragma unroll 4
    for (int i = 0; i < 32; i++) {
        int nn = wi * 32 + i;
        int nd = blockIdx.x * 128 + nn;
        if (nd >= N_NODES) break;
        float4 acc = bias;
#pragma unroll
        for (int k = 0; k < F_IN; k++) {
            float a = sa[nn][k];
            float4 w = *(const float4*)&sw[k][f];
            acc.x = fmaf(a, w.x, acc.x);
            acc.y = fmaf(a, w.y, acc.y);
            acc.z = fmaf(a, w.z, acc.z);
            acc.w = fmaf(a, w.w, acc.w);
        }
        float di = sdi[nn];
        uint2 st;
        *(__half2*)&st.x = __floats2half2_rn(fmaxf(acc.x, 0.f) * di, fmaxf(acc.y, 0.f) * di);
        *(__half2*)&st.y = __floats2half2_rn(fmaxf(acc.z, 0.f) * di, fmaxf(acc.w, 0.f) * di);
        *(uint2*)&g_h1h[nd * HID + f] = st;
    }
}

// ---- layer-2 aggregation of h1' + mean-pool accumulation ----
// warp per 8 nodes; 16-lane groups on even/odd edges; lane owns 8 features
__global__ void __launch_bounds__(256) k_aggpool(const int* __restrict__ batch) {
    int tid = threadIdx.x;
    int wi = tid >> 5, l = tid & 31;
    int group = l >> 4;            // 0: even edges, 1: odd edges
    int fl = (l & 15) * 8;         // feature base (8 halves)
    int node0 = blockIdx.x * 64 + wi * 8;

    int gprev = -1;
    float r0 = 0.f, r1 = 0.f, r2 = 0.f, r3 = 0.f;
    int fbase = fl + group * 4;

#pragma unroll 1
    for (int i = 0; i < 8; i++) {
        int node = node0 + i;
        if (node >= N_NODES) break;
        float a0, a1, a2, a3, a4, a5, a6, a7;
        {
            float sw0 = (group == 0) ? 1.f : 0.f;
            uint4 hs = *(const uint4*)&g_h1h[node * HID + fl];
            float2 s01 = __half22float2(*(__half2*)&hs.x);
            float2 s23 = __half22float2(*(__half2*)&hs.y);
            float2 s45 = __half22float2(*(__half2*)&hs.z);
            float2 s67 = __half22float2(*(__half2*)&hs.w);
            a0 = s01.x * sw0; a1 = s01.y * sw0;
            a2 = s23.x * sw0; a3 = s23.y * sw0;
            a4 = s45.x * sw0; a5 = s45.y * sw0;
            a6 = s67.x * sw0; a7 = s67.y * sw0;
        }
        int rs = g_rowptr[node], re = g_rowptr[node + 1];
        for (int e0 = rs; e0 < re; e0 += 32) {
            int ec = min(32, re - e0);
            int cs = (e0 + l < re) ? g_csr[e0 + l] : N_NODES;   // sentinel -> zero row
            int jmax = (ec + 1) >> 1;
#pragma unroll 4
            for (int j = 0; j < jmax; j++) {
                int sl = 2 * j + group;
                int s = __shfl_sync(0xffffffffu, cs, sl);
                uint4 hv = *(const uint4*)&g_h1h[s * HID + fl];
                float2 h01 = __half22float2(*(__half2*)&hv.x);
                float2 h23 = __half22float2(*(__half2*)&hv.y);
                float2 h45 = __half22float2(*(__half2*)&hv.z);
                float2 h67 = __half22float2(*(__half2*)&hv.w);
                a0 += h01.x; a1 += h01.y;
                a2 += h23.x; a3 += h23.y;
                a4 += h45.x; a5 += h45.y;
                a6 += h67.x; a7 += h67.y;
            }
        }
        a0 += __shfl_xor_sync(0xffffffffu, a0, 16);
        a1 += __shfl_xor_sync(0xffffffffu, a1, 16);
        a2 += __shfl_xor_sync(0xffffffffu, a2, 16);
        a3 += __shfl_xor_sync(0xffffffffu, a3, 16);
        a4 += __shfl_xor_sync(0xffffffffu, a4, 16);
        a5 += __shfl_xor_sync(0xffffffffu, a5, 16);
        a6 += __shfl_xor_sync(0xffffffffu, a6, 16);
        a7 += __shfl_xor_sync(0xffffffffu, a7, 16);
        float di = g_dinv[node];
        float v0 = (group ? a4 : a0) * di;
        float v1 = (group ? a5 : a1) * di;
        float v2 = (group ? a6 : a2) * di;
        float v3 = (group ? a7 : a3) * di;

        int g = batch[node];
        if (g != gprev) {
            if (gprev >= 0) {
                atomicAdd(&g_q[gprev * HID + fbase + 0], r0);
                atomicAdd(&g_q[gprev * HID + fbase + 1], r1);
                atomicAdd(&g_q[gprev * HID + fbase + 2], r2);
                atomicAdd(&g_q[gprev * HID + fbase + 3], r3);
            }
            gprev = g; r0 = r1 = r2 = r3 = 0.f;
        }
        r0 += v0; r1 += v1; r2 += v2; r3 += v3;
    }
    if (gprev >= 0) {
        atomicAdd(&g_q[gprev * HID + fbase + 0], r0);
        atomicAdd(&g_q[gprev * HID + fbase + 1], r1);
        atomicAdd(&g_q[gprev * HID + fbase + 2], r2);
        atomicAdd(&g_q[gprev * HID + fbase + 3], r3);
    }
}

// out = (q[g] @ Wc) / max(cnt,1) + bc ; then reset scratch for the next call
__global__ void k_final(float* __restrict__ out) {
    int g = blockIdx.x;
    int o = threadIdx.x;
    __shared__ float sp[HID];
    float cntv = g_gcnt[g];
    for (int k = o; k < HID; k += 32) sp[k] = g_q[g * HID + k];
    __syncthreads();
    // reset scratch (reads are done)
    for (int k = o; k < HID; k += 32) g_q[g * HID + k] = 0.f;
    if (o == 0) g_gcnt[g] = 0.f;
    {
        int idx = g * 32 + o;
        if (idx < N_NODES) { g_cnt[idx] = 0; g_fill[idx] = 0; }
    }
    float inv = 1.f / fmaxf(cntv, 1.f);
    if (o < F_OUT) {
        float acc = 0.f;
#pragma unroll 8
        for (int k = 0; k < HID; k++) acc = fmaf(sp[k], g_Wc[k * F_OUT + o], acc);
        out[g * F_OUT + o] = acc * inv + g_bc[o];
    }
}

// ---------------- launch ----------------
extern "C" void kernel_launch(void* const* d_in, const int* in_sizes, int n_in,
                              void* d_out, int out_size) {
    const float* x    = (const float*)d_in[0];
    const int*   esrc = (const int*)d_in[1];
    const int*   edst = (const int*)d_in[2];
    const int*   batch= (const int*)d_in[3];
    const float* W1   = (const float*)d_in[4];
    const float* b1   = (const float*)d_in[5];
    const float* W2   = (const float*)d_in[6];
    const float* b2   = (const float*)d_in[7];
    const float* Wlin = (const float*)d_in[8];
    const float* blin = (const float*)d_in[9];
    float* out = (float*)d_out;

    k_count<<<512, 256>>>(edst, batch);
    k_scan1<<<SCAN_NBLK, 1024>>>();
    k_scan23<<<(N_NODES + 255) / 256, 256>>>(x, W2, b2, Wlin, blin);
    k_fill<<<1024, 256>>>(esrc, edst);
    k_layer1<<<(N_NODES + 127) / 128, 128>>>(W1, b1);
    k_aggpool<<<(N_NODES + 63) / 64, 256>>>(batch);
    k_final<<<NUM_GRAPHS, 32>>>(out);
}

// round 17
// speedup vs baseline: 1.7299x; 1.0339x over previous
#include <cuda_runtime.h>
#include <cuda_fp16.h>

#define N_NODES 100000
#define N_EDGES 1600000
#define NUM_GRAPHS 4096
#define HID 128
#define F_IN 11
#define F_PAD 12
#define F_OUT 19

#define SCAN_CHUNK 2048
#define SCAN_NBLK ((N_NODES + SCAN_CHUNK - 1) / SCAN_CHUNK)   // 49

// ---------------- scratch (static device globals; no allocation) ----------------
// Invariant: g_cnt, g_q, g_gcnt are ZERO at kernel_launch entry.
// (zero-initialized at module load; k_final re-zeroes them at the end of every call)
__device__ int    g_cnt[N_NODES];
__device__ float  g_dinv[N_NODES];
__device__ int    g_rowptr[N_NODES + 1];
__device__ int    g_pos[N_EDGES];                  // within-row slot per edge (from k_count)
__device__ int    g_csr[N_EDGES];                  // src only
__device__ float  g_x12[N_NODES * F_PAD];          // x * dinv, padded to 12
__device__ __half g_h1h[(N_NODES + 1) * HID];      // h1' = relu(h1)*dinv; last row stays 0 (sentinel)
__device__ float  g_q[NUM_GRAPHS * HID];           // pooled aggregated h1'
__device__ float  g_gcnt[NUM_GRAPHS];
__device__ float  g_Wc[HID * F_OUT];               // W2 @ Wlin
__device__ float  g_bc[F_OUT];                     // b2 @ Wlin + blin
__device__ int    g_bsum[64];

// ---------------- kernels ----------------

// edge in-degree count (atomic old value = CSR slot!) + per-graph node count
__global__ void k_count(const int* __restrict__ dst, const int* __restrict__ batch) {
    int i = blockIdx.x * blockDim.x + threadIdx.x;
    int stride = gridDim.x * blockDim.x;
    const int4* dst4 = (const int4*)dst;
    int4* pos4 = (int4*)g_pos;
    for (int e = i; e < N_EDGES / 4; e += stride) {
        int4 d = dst4[e];
        int4 p;
        p.x = atomicAdd(&g_cnt[d.x], 1);
        p.y = atomicAdd(&g_cnt[d.y], 1);
        p.z = atomicAdd(&g_cnt[d.z], 1);
        p.w = atomicAdd(&g_cnt[d.w], 1);
        pos4[e] = p;
    }
    const int4* b4 = (const int4*)batch;
    for (int n = i; n < N_NODES / 4; n += stride) {
        int4 b = b4[n];
        if (b.x == b.w) {
            atomicAdd(&g_gcnt[b.x], 4.f);
        } else {
            atomicAdd(&g_gcnt[b.x], 1.f);
            atomicAdd(&g_gcnt[b.y], 1.f);
            atomicAdd(&g_gcnt[b.z], 1.f);
            atomicAdd(&g_gcnt[b.w], 1.f);
        }
    }
}

// ---- scan phase 1 (+ dinv fused) ----
__global__ void k_scan1() {
    __shared__ int sm[1024];
    int t = threadIdx.x;
    int base = blockIdx.x * SCAN_CHUNK;
    int i0 = base + 2 * t, i1 = i0 + 1;
    int v0 = (i0 < N_NODES) ? g_cnt[i0] : 0;
    int v1 = (i1 < N_NODES) ? g_cnt[i1] : 0;
    if (i0 < N_NODES) g_dinv[i0] = rsqrtf((float)(v0 + 1));
    if (i1 < N_NODES) g_dinv[i1] = rsqrtf((float)(v1 + 1));
    int s = v0 + v1;
    sm[t] = s;
    __syncthreads();
    for (int off = 1; off < 1024; off <<= 1) {
        int add = (t >= off) ? sm[t - off] : 0;
        __syncthreads();
        sm[t] += add;
        __syncthreads();
    }
    int excl = sm[t] - s;
    if (i0 < N_NODES) g_rowptr[i0] = excl;
    if (i1 < N_NODES) g_rowptr[i1] = excl + v0;
    if (t == 1023) g_bsum[blockIdx.x] = sm[t];
}

// ---- scan fixup + x12 = x*dinv build + Wc/bc precompute ----
__global__ void k_scan23(const float* __restrict__ x,
                         const float* __restrict__ W2, const float* __restrict__ b2,
                         const float* __restrict__ Wlin, const float* __restrict__ blin) {
    __shared__ int sm[64];
    int t = threadIdx.x;
    if (t < 64) sm[t] = (t < SCAN_NBLK) ? g_bsum[t] : 0;
    __syncthreads();
    if (t == 0) {
        int run = 0;
#pragma unroll
        for (int j = 0; j < SCAN_NBLK; j++) { int v = sm[j]; sm[j] = run; run += v; }
    }
    __syncthreads();
    int i = blockIdx.x * blockDim.x + t;
    if (i < N_NODES) g_rowptr[i] += sm[i >> 11];
    if (i == 0) g_rowptr[N_NODES] = N_EDGES;

    int stride = gridDim.x * blockDim.x;
    // x12 = x * dinv, padded to 12 floats/row
    for (int n = i; n < N_NODES; n += stride) {
        float di = g_dinv[n];
        float r[F_PAD];
#pragma unroll
        for (int f = 0; f < F_IN; f++) r[f] = x[n * F_IN + f] * di;
        r[11] = 0.f;
        *(float4*)&g_x12[n * F_PAD]     = make_float4(r[0], r[1], r[2],  r[3]);
        *(float4*)&g_x12[n * F_PAD + 4] = make_float4(r[4], r[5], r[6],  r[7]);
        *(float4*)&g_x12[n * F_PAD + 8] = make_float4(r[8], r[9], r[10], r[11]);
    }
    // Wc = W2 @ Wlin ; bc = b2 @ Wlin + blin
    for (int j = i; j < HID * F_OUT + F_OUT; j += stride) {
        if (j < HID * F_OUT) {
            int k = j / F_OUT, o = j - k * F_OUT;
            float s = 0.f;
#pragma unroll 8
            for (int m = 0; m < HID; m++) s = fmaf(W2[k * HID + m], Wlin[m * F_OUT + o], s);
            g_Wc[j] = s;
        } else {
            int o = j - HID * F_OUT;
            float s = blin[o];
#pragma unroll 8
            for (int m = 0; m < HID; m++) s = fmaf(b2[m], Wlin[m * F_OUT + o], s);
            g_bc[o] = s;
        }
    }
}

// CSR fill — atomic-free: slot precomputed in k_count
__global__ void k_fill(const int* __restrict__ src, const int* __restrict__ dst) {
    int i = blockIdx.x * blockDim.x + threadIdx.x;
    int stride = gridDim.x * blockDim.x;
    const int4* src4 = (const int4*)src;
    const int4* dst4 = (const int4*)dst;
    const int4* pos4 = (const int4*)g_pos;
    for (int e = i; e < N_EDGES / 4; e += stride) {
        int4 s = src4[e];
        int4 d = dst4[e];
        int4 p = pos4[e];
        g_csr[g_rowptr[d.x] + p.x] = s.x;
        g_csr[g_rowptr[d.y] + p.y] = s.y;
        g_csr[g_rowptr[d.z] + p.z] = s.z;
        g_csr[g_rowptr[d.w] + p.w] = s.w;
    }
}

// ---- layer 1: aggregate x' -> smem -> warp GEMM -> relu*dinv -> fp16 gmem ----
__global__ void __launch_bounds__(128) k_layer1(const float* __restrict__ W1,
                                                const float* __restrict__ b1) {
    __shared__ float sw[F_IN][HID];
    __shared__ float sb[HID];
    __shared__ float sa[128][13];
    __shared__ float sdi[128];
    int tid = threadIdx.x;
    for (int j = tid; j < F_IN * HID; j += 128) sw[j / HID][j % HID] = W1[j];
    for (int j = tid; j < HID; j += 128) sb[j] = b1[j];

    int node = blockIdx.x * 128 + tid;
    if (node < N_NODES) {
        float di = g_dinv[node];
        sdi[tid] = di;
        float4 a0 = *(const float4*)&g_x12[node * F_PAD];
        float4 a1 = *(const float4*)&g_x12[node * F_PAD + 4];
        float4 a2 = *(const float4*)&g_x12[node * F_PAD + 8];
        int rs = g_rowptr[node], re = g_rowptr[node + 1];
#pragma unroll 2
        for (int e = rs; e < re; e++) {
            int s = g_csr[e];
            float4 x0 = *(const float4*)&g_x12[s * F_PAD];
            float4 x1 = *(const float4*)&g_x12[s * F_PAD + 4];
            float4 x2 = *(const float4*)&g_x12[s * F_PAD + 8];
            a0.x += x0.x; a0.y += x0.y; a0.z += x0.z; a0.w += x0.w;
            a1.x += x1.x; a1.y += x1.y; a1.z += x1.z; a1.w += x1.w;
            a2.x += x2.x; a2.y += x2.y; a2.z += x2.z;
        }
        sa[tid][0] = a0.x * di; sa[tid][1] = a0.y * di; sa[tid][2]  = a0.z * di; sa[tid][3] = a0.w * di;
        sa[tid][4] = a1.x * di; sa[tid][5] = a1.y * di; sa[tid][6]  = a1.z * di; sa[tid][7] = a1.w * di;
        sa[tid][8] = a2.x * di; sa[tid][9] = a2.y * di; sa[tid][10] = a2.z * di;
    }
    __syncthreads();

    int wi = tid >> 5, l = tid & 31;
    int f = l * 4;
    float4 bias = *(const float4*)&sb[f];
#pragma unroll 4
    for (int i = 0; i < 32; i++) {
        int nn = wi * 32 + i;
        int nd = blockIdx.x * 128 + nn;
        if (nd >= N_NODES) break;
        float4 acc = bias;
#pragma unroll
        for (int k = 0; k < F_IN; k++) {
            float a = sa[nn][k];
            float4 w = *(const float4*)&sw[k][f];
            acc.x = fmaf(a, w.x, acc.x);
            acc.y = fmaf(a, w.y, acc.y);
            acc.z = fmaf(a, w.z, acc.z);
            acc.w = fmaf(a, w.w, acc.w);
        }
        float di = sdi[nn];
        uint2 st;
        *(__half2*)&st.x = __floats2half2_rn(fmaxf(acc.x, 0.f) * di, fmaxf(acc.y, 0.f) * di);
        *(__half2*)&st.y = __floats2half2_rn(fmaxf(acc.z, 0.f) * di, fmaxf(acc.w, 0.f) * di);
        *(uint2*)&g_h1h[nd * HID + f] = st;
    }
}

// ---- layer-2 aggregation of h1' + mean-pool accumulation ----
// warp per 8 nodes; 16-lane groups on even/odd edges; lane owns 8 features
__global__ void __launch_bounds__(256) k_aggpool(const int* __restrict__ batch) {
    int tid = threadIdx.x;
    int wi = tid >> 5, l = tid & 31;
    int group = l >> 4;            // 0: even edges, 1: odd edges
    int fl = (l & 15) * 8;         // feature base (8 halves)
    int node0 = blockIdx.x * 64 + wi * 8;

    int gprev = -1;
    float r0 = 0.f, r1 = 0.f, r2 = 0.f, r3 = 0.f;
    int fbase = fl + group * 4;

#pragma unroll 1
    for (int i = 0; i < 8; i++) {
        int node = node0 + i;
        if (node >= N_NODES) break;
        float a0, a1, a2, a3, a4, a5, a6, a7;
        {
            float sw0 = (group == 0) ? 1.f : 0.f;
            uint4 hs = *(const uint4*)&g_h1h[node * HID + fl];
            float2 s01 = __half22float2(*(__half2*)&hs.x);
            float2 s23 = __half22float2(*(__half2*)&hs.y);
            float2 s45 = __half22float2(*(__half2*)&hs.z);
            float2 s67 = __half22float2(*(__half2*)&hs.w);
            a0 = s01.x * sw0; a1 = s01.y * sw0;
            a2 = s23.x * sw0; a3 = s23.y * sw0;
            a4 = s45.x * sw0; a5 = s45.y * sw0;
            a6 = s67.x * sw0; a7 = s67.y * sw0;
        }
        int rs = g_rowptr[node], re = g_rowptr[node + 1];
        for (int e0 = rs; e0 < re; e0 += 32) {
            int ec = min(32, re - e0);
            int cs = (e0 + l < re) ? g_csr[e0 + l] : N_NODES;   // sentinel -> zero row
            int jmax = (ec + 1) >> 1;
#pragma unroll 4
            for (int j = 0; j < jmax; j++) {
                int sl = 2 * j + group;
                int s = __shfl_sync(0xffffffffu, cs, sl);
                uint4 hv = *(const uint4*)&g_h1h[s * HID + fl];
                float2 h01 = __half22float2(*(__half2*)&hv.x);
                float2 h23 = __half22float2(*(__half2*)&hv.y);
                float2 h45 = __half22float2(*(__half2*)&hv.z);
                float2 h67 = __half22float2(*(__half2*)&hv.w);
                a0 += h01.x; a1 += h01.y;
                a2 += h23.x; a3 += h23.y;
                a4 += h45.x; a5 += h45.y;
                a6 += h67.x; a7 += h67.y;
            }
        }
        a0 += __shfl_xor_sync(0xffffffffu, a0, 16);
        a1 += __shfl_xor_sync(0xffffffffu, a1, 16);
        a2 += __shfl_xor_sync(0xffffffffu, a2, 16);
        a3 += __shfl_xor_sync(0xffffffffu, a3, 16);
        a4 += __shfl_xor_sync(0xffffffffu, a4, 16);
        a5 += __shfl_xor_sync(0xffffffffu, a5, 16);
        a6 += __shfl_xor_sync(0xffffffffu, a6, 16);
        a7 += __shfl_xor_sync(0xffffffffu, a7, 16);
        float di = g_dinv[node];
        float v0 = (group ? a4 : a0) * di;
        float v1 = (group ? a5 : a1) * di;
        float v2 = (group ? a6 : a2) * di;
        float v3 = (group ? a7 : a3) * di;

        int g = batch[node];
        if (g != gprev) {
            if (gprev >= 0) {
                atomicAdd(&g_q[gprev * HID + fbase + 0], r0);
                atomicAdd(&g_q[gprev * HID + fbase + 1], r1);
                atomicAdd(&g_q[gprev * HID + fbase + 2], r2);
                atomicAdd(&g_q[gprev * HID + fbase + 3], r3);
            }
            gprev = g; r0 = r1 = r2 = r3 = 0.f;
        }
        r0 += v0; r1 += v1; r2 += v2; r3 += v3;
    }
    if (gprev >= 0) {
        atomicAdd(&g_q[gprev * HID + fbase + 0], r0);
        atomicAdd(&g_q[gprev * HID + fbase + 1], r1);
        atomicAdd(&g_q[gprev * HID + fbase + 2], r2);
        atomicAdd(&g_q[gprev * HID + fbase + 3], r3);
    }
}

// out = (q[g] @ Wc) / max(cnt,1) + bc ; then reset scratch for the next call
__global__ void k_final(float* __restrict__ out) {
    int g = blockIdx.x;
    int o = threadIdx.x;
    __shared__ float sp[HID];
    float cntv = g_gcnt[g];
    for (int k = o; k < HID; k += 32) sp[k] = g_q[g * HID + k];
    __syncthreads();
    // reset scratch (reads are done)
    for (int k = o; k < HID; k += 32) g_q[g * HID + k] = 0.f;
    if (o == 0) g_gcnt[g] = 0.f;
    {
        int idx = g * 32 + o;
        if (idx < N_NODES) g_cnt[idx] = 0;
    }
    float inv = 1.f / fmaxf(cntv, 1.f);
    if (o < F_OUT) {
        float acc = 0.f;
#pragma unroll 8
        for (int k = 0; k < HID; k++) acc = fmaf(sp[k], g_Wc[k * F_OUT + o], acc);
        out[g * F_OUT + o] = acc * inv + g_bc[o];
    }
}

// ---------------- launch ----------------
extern "C" void kernel_launch(void* const* d_in, const int* in_sizes, int n_in,
                              void* d_out, int out_size) {
    const float* x    = (const float*)d_in[0];
    const int*   esrc = (const int*)d_in[1];
    const int*   edst = (const int*)d_in[2];
    const int*   batch= (const int*)d_in[3];
    const float* W1   = (const float*)d_in[4];
    const float* b1   = (const float*)d_in[5];
    const float* W2   = (const float*)d_in[6];
    const float* b2   = (const float*)d_in[7];
    const float* Wlin = (const float*)d_in[8];
    const float* blin = (const float*)d_in[9];
    float* out = (float*)d_out;

    k_count<<<1024, 256>>>(edst, batch);
    k_scan1<<<SCAN_NBLK, 1024>>>();
    k_scan23<<<(N_NODES + 255) / 256, 256>>>(x, W2, b2, Wlin, blin);
    k_fill<<<2048, 256>>>(esrc, edst);
    k_layer1<<<(N_NODES + 127) / 128, 128>>>(W1, b1);
    k_aggpool<<<(N_NODES + 63) / 64, 256>>>(batch);
    k_final<<<NUM_GRAPHS, 32>>>(out);
}